// round 10
// baseline (speedup 1.0000x reference)
#include <cuda_runtime.h>
#include <math.h>

#define Bsz 2048
#define Tt  512
#define Vv  64
#define Hh  256
#define HV  320          // H + V
#define BM  16           // batch rows per block
#define BMP 20           // padded row width (floats), 16B-aligned rows
#define NBLK (Bsz / BM)  // 128 blocks
#define NTHR 256         // 8 warps; each thread: 2 cols x 8 rows
#define NC   (HV / 4)    // 80 k-chunks

// theta packed: g_thetaT4[(k>>2)*(Hh*4) + h*4 + (k&3)]
__device__ __align__(16) float g_thetaT4[HV * Hh];

// ---------- packed f32x2 helpers ----------
__device__ __forceinline__ unsigned long long fma2(unsigned long long a,
                                                   unsigned long long b,
                                                   unsigned long long c) {
    unsigned long long d;
    asm("fma.rn.f32x2 %0, %1, %2, %3;" : "=l"(d) : "l"(a), "l"(b), "l"(c));
    return d;
}
__device__ __forceinline__ unsigned long long pack2(float x) {
    unsigned long long d;
    asm("mov.b64 %0, {%1, %1};" : "=l"(d) : "r"(__float_as_uint(x)));
    return d;
}
__device__ __forceinline__ void unpack2(unsigned long long v, float& lo, float& hi) {
    unsigned int a, b;
    asm("mov.b64 {%0, %1}, %2;" : "=r"(a), "=r"(b) : "l"(v));
    lo = __uint_as_float(a);
    hi = __uint_as_float(b);
}

// theta [H, H+V] row-major -> packed chunk layout
__global__ void transpose_kernel(const float* __restrict__ theta) {
    int idx = blockIdx.x * blockDim.x + threadIdx.x;
    if (idx >= HV * Hh) return;
    int k = idx >> 8;
    int h = idx & 255;
    g_thetaT4[(k >> 2) * (Hh * 4) + h * 4 + (k & 3)] = theta[h * HV + k];
}

// Persistent kernel: each block owns BM batch rows for ALL T steps.
// Thread layout: hb = tid & 127 -> cols (hb, hb+128); r0 = (tid>>7)*8 -> rows r0..r0+7.
__global__ void __launch_bounds__(NTHR, 1) rnn_persistent(
    const float* __restrict__ sf,        // [B, T, V]
    const float* __restrict__ bias_g,    // [1]
    const float* __restrict__ theta_dot, // [1, H]
    float* __restrict__ out)             // [B]
{
    __shared__ __align__(16) float st_p[HV][BMP];   // state+token, k-major: 25.6 KB
    __shared__ __align__(16) float z_s[BM][Hh];     // z scratch: 16 KB
    __shared__ float mean_s[BM];
    __shared__ float rstd_s[BM];

    const int tid  = threadIdx.x;
    const int hb   = tid & 127;          // column base (cols hb, hb+128)
    const int r0   = (tid >> 7) * 8;     // row group: rows r0..r0+7
    const int wid  = tid >> 5, lane = tid & 31;
    const int b0   = blockIdx.x * BM;

    // token-load mapping: thread -> (row m_t, float4 group v4)
    const int m_t = tid >> 4;            // 0..15
    const int v4  = (tid & 15) * 4;      // 0,4,..,60

    const float bval = bias_g[0];
    const float td0 = theta_dot[hb];
    const float td1 = theta_dot[hb + 128];

    // ---- zero initial state ----
    for (int idx = tid; idx < HV * BMP; idx += NTHR)
        (&st_p[0][0])[idx] = 0.0f;

    // ---- stage tokens for t=0 ----
    {
        float4 tk = *reinterpret_cast<const float4*>(
            &sf[((size_t)(b0 + m_t) * Tt + 0) * Vv + v4]);
        st_p[Hh + v4 + 0][m_t] = tk.x;
        st_p[Hh + v4 + 1][m_t] = tk.y;
        st_p[Hh + v4 + 2][m_t] = tk.z;
        st_p[Hh + v4 + 3][m_t] = tk.w;
    }

    const float4* th0 = reinterpret_cast<const float4*>(g_thetaT4) + hb;
    const float4* th1 = th0 + 128;

    float zr[16];   // [col(2)][row(8)]

    for (int t = 0; t < Tt; t++) {
        __syncthreads();   // (d) state + token writes visible

        // prefetch next token (overlaps GEMM)
        float4 tok;
        const bool havet = (t + 1 < Tt);
        if (havet) {
            tok = *reinterpret_cast<const float4*>(
                &sf[((size_t)(b0 + m_t) * Tt + (t + 1)) * Vv + v4]);
        }

        // ---------- GEMM: 2 cols x 8 rows per thread ----------
        unsigned long long acc[8];   // [col(2)][rowpair(4)]
#pragma unroll
        for (int j = 0; j < 8; j++) acc[j] = pack2(bval);

        // theta software pipeline, depth 2
        float4 a0c = th0[0],       a1c = th1[0];
        float4 a0n = th0[Hh],      a1n = th1[Hh];

#pragma unroll 4
        for (int c = 0; c < NC; c++) {
            // prefetch theta chunk c+2 (covers L2 latency ~250 cyc)
            int cf = (c + 2 < NC) ? c + 2 : c;
            float4 a0f = th0[cf * Hh];
            float4 a1f = th1[cf * Hh];

            // batch all st loads for this chunk (MLP=8 LDS.128)
            ulonglong2 s[8];
#pragma unroll
            for (int kk = 0; kk < 4; kk++) {
                s[2 * kk]     = *reinterpret_cast<const ulonglong2*>(
                    &st_p[c * 4 + kk][r0]);          // rows r0..r0+3
                s[2 * kk + 1] = *reinterpret_cast<const ulonglong2*>(
                    &st_p[c * 4 + kk][r0 + 4]);      // rows r0+4..r0+7
            }

            float t0a[4], t1a[4];
            *reinterpret_cast<float4*>(t0a) = a0c;
            *reinterpret_cast<float4*>(t1a) = a1c;
#pragma unroll
            for (int kk = 0; kk < 4; kk++) {
                unsigned long long p0 = pack2(t0a[kk]);
                unsigned long long p1 = pack2(t1a[kk]);
                ulonglong2 sA = s[2 * kk];
                ulonglong2 sB = s[2 * kk + 1];
                acc[0] = fma2(sA.x, p0, acc[0]);
                acc[1] = fma2(sA.y, p0, acc[1]);
                acc[2] = fma2(sB.x, p0, acc[2]);
                acc[3] = fma2(sB.y, p0, acc[3]);
                acc[4] = fma2(sA.x, p1, acc[4]);
                acc[5] = fma2(sA.y, p1, acc[5]);
                acc[6] = fma2(sB.x, p1, acc[6]);
                acc[7] = fma2(sB.y, p1, acc[7]);
            }

            a0c = a0n; a1c = a1n;
            a0n = a0f; a1n = a1f;
        }

        // unpack z, stage into z_s
#pragma unroll
        for (int j = 0; j < 8; j++) unpack2(acc[j], zr[2 * j], zr[2 * j + 1]);
#pragma unroll
        for (int rr = 0; rr < 8; rr++) {
            z_s[r0 + rr][hb]       = zr[rr];        // col hb
            z_s[r0 + rr][hb + 128] = zr[8 + rr];    // col hb+128
        }

        __syncthreads();   // (b) z_s ready; st_p GEMM reads done

        // ---------- per-row mean / Bessel std: 8 warps x 2 rows ----------
        for (int m = wid; m < BM; m += 8) {
            float s = 0.0f, ss = 0.0f;
#pragma unroll
            for (int j = 0; j < Hh / 32; j++) {
                float v = z_s[m][j * 32 + lane];
                s += v;
                ss = fmaf(v, v, ss);
            }
#pragma unroll
            for (int off = 16; off; off >>= 1) {
                s  += __shfl_xor_sync(0xffffffffu, s, off);
                ss += __shfl_xor_sync(0xffffffffu, ss, off);
            }
            if (lane == 0) {
                float mean = s * (1.0f / Hh);
                float var  = (ss - (float)Hh * mean * mean) * (1.0f / (Hh - 1));
                var = fmaxf(var, 1e-30f);
                float r = rsqrtf(var);
                r = r * (1.5f - 0.5f * var * r * r);   // Newton refine
                mean_s[m] = mean;
                rstd_s[m] = r;
            }
        }

        // stage next tokens (st_p token rows free after bar (b))
        if (havet) {
            st_p[Hh + v4 + 0][m_t] = tok.x;
            st_p[Hh + v4 + 1][m_t] = tok.y;
            st_p[Hh + v4 + 2][m_t] = tok.z;
            st_p[Hh + v4 + 3][m_t] = tok.w;
        }

        __syncthreads();   // (c) mean/rstd ready

        // ---------- layernorm apply + relu, write state (vectorized STS.128) ----------
        {
            float mn[8], rs[8];
#pragma unroll
            for (int rr = 0; rr < 8; rr++) { mn[rr] = mean_s[r0 + rr]; rs[rr] = rstd_s[r0 + rr]; }
#pragma unroll
            for (int rr = 0; rr < 8; rr++) {
                zr[rr]     = fmaxf((zr[rr]     - mn[rr]) * rs[rr], 0.0f);
                zr[8 + rr] = fmaxf((zr[8 + rr] - mn[rr]) * rs[rr], 0.0f);
            }
            *reinterpret_cast<float4*>(&st_p[hb][r0])           = make_float4(zr[0], zr[1], zr[2], zr[3]);
            *reinterpret_cast<float4*>(&st_p[hb][r0 + 4])       = make_float4(zr[4], zr[5], zr[6], zr[7]);
            *reinterpret_cast<float4*>(&st_p[hb + 128][r0])     = make_float4(zr[8], zr[9], zr[10], zr[11]);
            *reinterpret_cast<float4*>(&st_p[hb + 128][r0 + 4]) = make_float4(zr[12], zr[13], zr[14], zr[15]);
        }
    }

    // ---------- logits: out[b] = sigmoid(sum_h state[b,h] * theta_dot[h]) ----------
#pragma unroll
    for (int rr = 0; rr < 8; rr++) {
        z_s[r0 + rr][hb]       = zr[rr]     * td0;
        z_s[r0 + rr][hb + 128] = zr[8 + rr] * td1;
    }
    __syncthreads();

    for (int m = wid; m < BM; m += 8) {
        float s = 0.0f;
#pragma unroll
        for (int j = 0; j < Hh / 32; j++) s += z_s[m][j * 32 + lane];
#pragma unroll
        for (int off = 16; off; off >>= 1)
            s += __shfl_xor_sync(0xffffffffu, s, off);
        if (lane == 0) out[b0 + m] = 1.0f / (1.0f + expf(-s));
    }
}

extern "C" void kernel_launch(void* const* d_in, const int* in_sizes, int n_in,
                              void* d_out, int out_size) {
    const float* sf        = (const float*)d_in[0];
    const float* theta     = (const float*)d_in[1];
    const float* bias      = (const float*)d_in[2];
    const float* theta_dot = (const float*)d_in[3];
    float*       out       = (float*)d_out;

    transpose_kernel<<<HV, 256>>>(theta);
    rnn_persistent<<<NBLK, NTHR>>>(sf, bias, theta_dot, out);
}